// round 12
// baseline (speedup 1.0000x reference)
#include <cuda_runtime.h>
#include <cuda_bf16.h>
#include <cstdint>

// GraphConv: out = segment_sum(feat[src] -> dst) @ W_neigh + b_neigh + feat @ W_self
// N = 100000 nodes, D = 128, E = 600000 edges.
// Harness downcasts int64 indices to int32 — src/dst are const int*.
// SINGLE STREAM ONLY: side-stream forks are not captured by the harness graph
// (R11 failure: out left poisoned because forked GEMMs never entered the graph).

#define D_FEAT 128
#define N_NODES_MAX 100000

// Aggregation scratch (51.2 MB). float4 type guarantees 16-byte alignment.
__device__ float4 g_agg4[(size_t)N_NODES_MAX * (D_FEAT / 4)];

#define ASTRIDE 136            // bf16 elems per padded row (272 B; 272 % 16 == 0)
#define TILE_BF16 (128 * ASTRIDE)                 // 17408 bf16 elems = 34816 B
#define TILE_U4 (TILE_BF16 * 2 / 16)              // 2176 uint4 per hi or lo tile
#define GEMM_SMEM_BYTES (4 * TILE_BF16 * 2)       // Ahi,Alo,Whi,Wlo = 139264 B

// Pre-converted weights, padded layout [128][ASTRIDE]: [0..TILE_U4) = hi, rest = lo.
__device__ uint4 g_Wn_hilo[2 * TILE_U4];
__device__ uint4 g_Ws_hilo[2 * TILE_U4];

// ---------------------------------------------------------------------------
// helpers
// ---------------------------------------------------------------------------
__device__ __forceinline__ uint32_t smem_u32(const void* p) {
    return (uint32_t)__cvta_generic_to_shared(p);
}
__device__ __forceinline__ void ldm_x4(uint32_t* r, uint32_t addr) {
    asm volatile("ldmatrix.sync.aligned.m8n8.x4.shared.b16 {%0,%1,%2,%3}, [%4];"
                 : "=r"(r[0]), "=r"(r[1]), "=r"(r[2]), "=r"(r[3]) : "r"(addr));
}
__device__ __forceinline__ void ldm_x4_trans(uint32_t* r, uint32_t addr) {
    asm volatile("ldmatrix.sync.aligned.m8n8.x4.trans.shared.b16 {%0,%1,%2,%3}, [%4];"
                 : "=r"(r[0]), "=r"(r[1]), "=r"(r[2]), "=r"(r[3]) : "r"(addr));
}
__device__ __forceinline__ void mma16816(float* c, const uint32_t* a, const uint32_t* b) {
    asm volatile("mma.sync.aligned.m16n8k16.row.col.f32.bf16.bf16.f32 "
                 "{%0,%1,%2,%3}, {%4,%5,%6,%7}, {%8,%9}, {%0,%1,%2,%3};"
                 : "+f"(c[0]), "+f"(c[1]), "+f"(c[2]), "+f"(c[3])
                 : "r"(a[0]), "r"(a[1]), "r"(a[2]), "r"(a[3]), "r"(b[0]), "r"(b[1]));
}
// pack two floats as bf16x2: low half = e0, high half = e1
__device__ __forceinline__ uint32_t packbf2(float e0, float e1) {
    uint32_t r;
    asm("cvt.rn.bf16x2.f32 %0, %1, %2;" : "=r"(r) : "f"(e1), "f"(e0));
    return r;
}
__device__ __forceinline__ float bf16_round(float x) {
    return __bfloat162float(__float2bfloat16_rn(x));
}

// ---------------------------------------------------------------------------
// Kernel 0: pre-convert both weight matrices to padded hi/lo bf16 (1 block).
// ---------------------------------------------------------------------------
__global__ void convert_w_kernel(const float* __restrict__ Wn,
                                 const float* __restrict__ Ws) {
    int t = threadIdx.x;
    __nv_bfloat16* nh = reinterpret_cast<__nv_bfloat16*>(g_Wn_hilo);
    __nv_bfloat16* nl = nh + TILE_BF16;
    __nv_bfloat16* sh = reinterpret_cast<__nv_bfloat16*>(g_Ws_hilo);
    __nv_bfloat16* sl = sh + TILE_BF16;
#pragma unroll 4
    for (int i = 0; i < 16; ++i) {
        int idx4 = i * 256 + t;
        int row = idx4 >> 5;
        int col = (idx4 & 31) << 2;
        int so = row * ASTRIDE + col;

        float4 w = *reinterpret_cast<const float4*>(Wn + (size_t)row * 128 + col);
        float h0 = bf16_round(w.x), h1 = bf16_round(w.y);
        float h2 = bf16_round(w.z), h3 = bf16_round(w.w);
        *reinterpret_cast<uint2*>(nh + so) = make_uint2(packbf2(h0, h1), packbf2(h2, h3));
        *reinterpret_cast<uint2*>(nl + so) =
            make_uint2(packbf2(w.x - h0, w.y - h1), packbf2(w.z - h2, w.w - h3));

        float4 v = *reinterpret_cast<const float4*>(Ws + (size_t)row * 128 + col);
        float g0 = bf16_round(v.x), g1 = bf16_round(v.y);
        float g2 = bf16_round(v.z), g3 = bf16_round(v.w);
        *reinterpret_cast<uint2*>(sh + so) = make_uint2(packbf2(g0, g1), packbf2(g2, g3));
        *reinterpret_cast<uint2*>(sl + so) =
            make_uint2(packbf2(v.x - g0, v.y - g1), packbf2(v.z - g2, v.w - g3));
    }
}

// ---------------------------------------------------------------------------
// Kernel 1: zero the aggregation buffer.
// ---------------------------------------------------------------------------
__global__ void zero_agg_kernel(int total4) {
    int i = blockIdx.x * blockDim.x + threadIdx.x;
    float4 z = make_float4(0.f, 0.f, 0.f, 0.f);
    for (; i < total4; i += gridDim.x * blockDim.x) {
        g_agg4[i] = z;
    }
}

// ---------------------------------------------------------------------------
// Kernel 2: scatter-add. One warp per edge; vector RED into L2-resident agg.
// ---------------------------------------------------------------------------
__global__ void scatter_kernel(const float* __restrict__ feat,
                               const int* __restrict__ src,
                               const int* __restrict__ dst,
                               int n_edges, int n_nodes) {
    int warps_per_block = blockDim.x >> 5;
    int e = blockIdx.x * warps_per_block + (threadIdx.x >> 5);
    if (e >= n_edges) return;
    int lane = threadIdx.x & 31;

    int s = src[e];
    int d = dst[e];
    if ((unsigned)s >= (unsigned)n_nodes || (unsigned)d >= (unsigned)n_nodes) return;

    const float4* fsrc = reinterpret_cast<const float4*>(feat) + (size_t)s * (D_FEAT / 4);
    float4 v = fsrc[lane];

    float4* dstp = g_agg4 + (size_t)d * (D_FEAT / 4) + lane;
    asm volatile("red.global.add.v4.f32 [%0], {%1, %2, %3, %4};"
                 :: "l"(dstp), "f"(v.x), "f"(v.y), "f"(v.z), "f"(v.w)
                 : "memory");
}

// ---------------------------------------------------------------------------
// Kernel 3: fused dual split-bf16 tensor-core GEMM + bias.
//   out = agg @ Wn + feat @ Ws + b, each product via 3-term bf16 split:
//   A@W ~= Ahi@Whi + Ahi@Wlo + Alo@Whi   (lo*lo ~ 4e-6 rel, dropped)
// 128x128 tile, 256 threads (8 warps: 2 m-groups x 4 n-groups), K=128 staged.
// W tiles come pre-converted from device globals (straight uint4 copy).
// ---------------------------------------------------------------------------
__global__ __launch_bounds__(256)
void gemm_kernel(const float* __restrict__ feat,
                 const float* __restrict__ bn,
                 float* __restrict__ out,
                 int n_nodes) {
    extern __shared__ char smem[];
    __nv_bfloat16* Ahi = reinterpret_cast<__nv_bfloat16*>(smem);
    __nv_bfloat16* Alo = Ahi + TILE_BF16;
    __nv_bfloat16* Whi = Alo + TILE_BF16;   // Whi+Wlo contiguous: one linear copy

    const uint32_t aHi_b = smem_u32(Ahi);
    const uint32_t aLo_b = smem_u32(Alo);
    const uint32_t wHi_b = smem_u32(Whi);
    const uint32_t wLo_b = wHi_b + TILE_BF16 * 2;

    int tid = threadIdx.x;
    int lane = tid & 31;
    int wid = tid >> 5;
    int wm = wid & 1;          // m-group: rows wm*64 .. +63
    int wn = wid >> 1;         // n-group: cols wn*32 .. +31
    int m0 = blockIdx.x * 128;

    int lrow = lane & 15;
    int lcolh = (lane >> 4) << 3;  // 0 or 8

    const float* aggf = reinterpret_cast<const float*>(g_agg4);

    float acc[4][4][4];
#pragma unroll
    for (int mi = 0; mi < 4; mi++)
#pragma unroll
        for (int ni = 0; ni < 4; ni++)
#pragma unroll
            for (int q = 0; q < 4; q++)
                acc[mi][ni][q] = 0.f;

    for (int half = 0; half < 2; ++half) {
        const float* Aglob = half ? feat : aggf;
        const uint4* Wsrc = half ? g_Ws_hilo : g_Wn_hilo;

        __syncthreads();  // previous half's smem reads done

        // ---- copy pre-converted W (hi then lo) into smem: 4352 uint4 ----
        {
            uint4* wdst = reinterpret_cast<uint4*>(Whi);
#pragma unroll
            for (int i = 0; i < 17; ++i) {
                int idx = i * 256 + tid;        // 17*256 = 4352 exactly
                wdst[idx] = Wsrc[idx];
            }
        }

        // ---- convert A tile to hi/lo bf16 in smem ----
#pragma unroll 4
        for (int it = 0; it < 16; ++it) {
            int idx4 = it * 256 + tid;
            int row = idx4 >> 5;
            int col = (idx4 & 31) << 2;

            int grow = m0 + row;
            if (grow >= n_nodes) grow = n_nodes - 1;   // clamp; stores guarded
            float4 v = *reinterpret_cast<const float4*>(Aglob + (size_t)grow * 128 + col);
            float h0 = bf16_round(v.x), h1 = bf16_round(v.y);
            float h2 = bf16_round(v.z), h3 = bf16_round(v.w);
            int so = row * ASTRIDE + col;
            *reinterpret_cast<uint2*>(Ahi + so) = make_uint2(packbf2(h0, h1), packbf2(h2, h3));
            *reinterpret_cast<uint2*>(Alo + so) =
                make_uint2(packbf2(v.x - h0, v.y - h1), packbf2(v.z - h2, v.w - h3));
        }
        __syncthreads();

        // ---- tensor-core compute over K=128 ----
#pragma unroll
        for (int ks = 0; ks < 8; ++ks) {
            int k0 = ks * 16;

            uint32_t ahi[4][4], alo[4][4];
#pragma unroll
            for (int mi = 0; mi < 4; ++mi) {
                uint32_t off = (uint32_t)((wm * 64 + mi * 16 + lrow) * ASTRIDE + k0 + lcolh) * 2;
                ldm_x4(ahi[mi], aHi_b + off);
                ldm_x4(alo[mi], aLo_b + off);
            }
            uint32_t bhi[4][2], blo[4][2];
#pragma unroll
            for (int nh = 0; nh < 2; ++nh) {
                uint32_t off = (uint32_t)((k0 + lrow) * ASTRIDE + wn * 32 + nh * 16 + lcolh) * 2;
                uint32_t t[4];
                ldm_x4_trans(t, wHi_b + off);
                bhi[2 * nh][0] = t[0]; bhi[2 * nh][1] = t[1];
                bhi[2 * nh + 1][0] = t[2]; bhi[2 * nh + 1][1] = t[3];
                ldm_x4_trans(t, wLo_b + off);
                blo[2 * nh][0] = t[0]; blo[2 * nh][1] = t[1];
                blo[2 * nh + 1][0] = t[2]; blo[2 * nh + 1][1] = t[3];
            }
#pragma unroll
            for (int mi = 0; mi < 4; ++mi)
#pragma unroll
                for (int ni = 0; ni < 4; ++ni) {
                    mma16816(acc[mi][ni], ahi[mi], bhi[ni]);
                    mma16816(acc[mi][ni], ahi[mi], blo[ni]);
                    mma16816(acc[mi][ni], alo[mi], bhi[ni]);
                }
        }
    }

    // ---- bias + store (fragment layout: rows g, g+8; cols 2tg, 2tg+1) ----
    int g = lane >> 2, tg = lane & 3;
#pragma unroll
    for (int ni = 0; ni < 4; ++ni) {
        int col = wn * 32 + ni * 8 + 2 * tg;
        float2 bv = *reinterpret_cast<const float2*>(bn + col);
#pragma unroll
        for (int mi = 0; mi < 4; ++mi) {
            int r0 = m0 + wm * 64 + mi * 16 + g;
            if (r0 < n_nodes) {
                float2 o = make_float2(acc[mi][ni][0] + bv.x, acc[mi][ni][1] + bv.y);
                *reinterpret_cast<float2*>(out + (size_t)r0 * 128 + col) = o;
            }
            int r1 = r0 + 8;
            if (r1 < n_nodes) {
                float2 o = make_float2(acc[mi][ni][2] + bv.x, acc[mi][ni][3] + bv.y);
                *reinterpret_cast<float2*>(out + (size_t)r1 * 128 + col) = o;
            }
        }
    }
}

// ---------------------------------------------------------------------------
// Launch (single stream, strictly serial — capture-safe).
// ---------------------------------------------------------------------------
extern "C" void kernel_launch(void* const* d_in, const int* in_sizes, int n_in,
                              void* d_out, int out_size) {
    const float* feat = (const float*)d_in[0];
    const int* src    = (const int*)d_in[1];   // int64 downcast to int32 by harness
    const int* dst    = (const int*)d_in[2];
    const float* Wn   = (const float*)d_in[3];
    const float* bn   = (const float*)d_in[4];
    const float* Ws   = (const float*)d_in[5];
    float* out        = (float*)d_out;

    int n_nodes = in_sizes[0] / D_FEAT;
    int n_edges = in_sizes[1];

    static bool attr_set = false;
    if (!attr_set) {
        cudaFuncSetAttribute(gemm_kernel,
                             cudaFuncAttributeMaxDynamicSharedMemorySize,
                             GEMM_SMEM_BYTES);
        attr_set = true;
    }

    // 0) pre-convert weights to hi/lo bf16 (1 block)
    convert_w_kernel<<<1, 256>>>(Wn, Ws);

    // 1) zero agg
    int total4 = n_nodes * (D_FEAT / 4);
    int zblocks = (total4 + 255) / 256;
    if (zblocks > 4096) zblocks = 4096;
    zero_agg_kernel<<<zblocks, 256>>>(total4);

    // 2) scatter-add (8 warps = 8 edges per block)
    int sblocks = (n_edges + 7) / 8;
    scatter_kernel<<<sblocks, 256>>>(feat, src, dst, n_edges, n_nodes);

    // 3) fused dual GEMM + bias
    int gblocks = (n_nodes + 127) / 128;
    gemm_kernel<<<gblocks, 256, GEMM_SMEM_BYTES>>>(feat, bn, out, n_nodes);
}

// round 13
// speedup vs baseline: 1.3961x; 1.3961x over previous
#include <cuda_runtime.h>
#include <cuda_bf16.h>
#include <cstdint>

// GraphConv: out = segment_sum(feat[src] -> dst) @ W_neigh + b_neigh + feat @ W_self
// N = 100000 nodes, D = 128, E = 600000 edges.
// Harness downcasts int64 indices to int32 — src/dst are const int*.
// SINGLE STREAM ONLY (R11: side-stream forks are dropped by harness capture).

#define D_FEAT 128
#define N_NODES_MAX 100000

// Aggregation scratch (51.2 MB). float4 type guarantees 16-byte alignment.
__device__ float4 g_agg4[(size_t)N_NODES_MAX * (D_FEAT / 4)];

#define ASTRIDE 136                        // bf16 elems per padded row (272 B)
#define BLK_M 64                           // output rows per CTA (occupancy: 2 CTAs/SM)
#define A_TILE_ELEMS (BLK_M * ASTRIDE)     // 8704 bf16 = 17408 B per buffer
#define W_TILE_ELEMS (128 * ASTRIDE)       // 17408 bf16 = 34816 B per buffer
#define W_TILE_U4 (W_TILE_ELEMS * 2 * 2 / 16)  // hi+lo = 4352 uint4
// smem: Ahi + Alo + Whi + Wlo = (2*8704 + 2*17408)*2 = 104448 B -> 2 CTAs/SM
#define GEMM_SMEM_BYTES ((2 * A_TILE_ELEMS + 2 * W_TILE_ELEMS) * 2)

// Pre-converted weights, padded layout [128][ASTRIDE]: first half hi, then lo.
__device__ uint4 g_Wn_hilo[W_TILE_U4];
__device__ uint4 g_Ws_hilo[W_TILE_U4];

// ---------------------------------------------------------------------------
// helpers
// ---------------------------------------------------------------------------
__device__ __forceinline__ uint32_t smem_u32(const void* p) {
    return (uint32_t)__cvta_generic_to_shared(p);
}
__device__ __forceinline__ void ldm_x4(uint32_t* r, uint32_t addr) {
    asm volatile("ldmatrix.sync.aligned.m8n8.x4.shared.b16 {%0,%1,%2,%3}, [%4];"
                 : "=r"(r[0]), "=r"(r[1]), "=r"(r[2]), "=r"(r[3]) : "r"(addr));
}
__device__ __forceinline__ void ldm_x4_trans(uint32_t* r, uint32_t addr) {
    asm volatile("ldmatrix.sync.aligned.m8n8.x4.trans.shared.b16 {%0,%1,%2,%3}, [%4];"
                 : "=r"(r[0]), "=r"(r[1]), "=r"(r[2]), "=r"(r[3]) : "r"(addr));
}
__device__ __forceinline__ void mma16816(float* c, const uint32_t* a, const uint32_t* b) {
    asm volatile("mma.sync.aligned.m16n8k16.row.col.f32.bf16.bf16.f32 "
                 "{%0,%1,%2,%3}, {%4,%5,%6,%7}, {%8,%9}, {%0,%1,%2,%3};"
                 : "+f"(c[0]), "+f"(c[1]), "+f"(c[2]), "+f"(c[3])
                 : "r"(a[0]), "r"(a[1]), "r"(a[2]), "r"(a[3]), "r"(b[0]), "r"(b[1]));
}
// pack two floats as bf16x2: low half = e0, high half = e1
__device__ __forceinline__ uint32_t packbf2(float e0, float e1) {
    uint32_t r;
    asm("cvt.rn.bf16x2.f32 %0, %1, %2;" : "=r"(r) : "f"(e1), "f"(e0));
    return r;
}
__device__ __forceinline__ float bf16_round(float x) {
    return __bfloat162float(__float2bfloat16_rn(x));
}

// ---------------------------------------------------------------------------
// Kernel 0: pre-convert both weight matrices to padded hi/lo bf16 (1 block).
// ---------------------------------------------------------------------------
__global__ void convert_w_kernel(const float* __restrict__ Wn,
                                 const float* __restrict__ Ws) {
    int t = threadIdx.x;
    __nv_bfloat16* nh = reinterpret_cast<__nv_bfloat16*>(g_Wn_hilo);
    __nv_bfloat16* nl = nh + W_TILE_ELEMS;
    __nv_bfloat16* sh = reinterpret_cast<__nv_bfloat16*>(g_Ws_hilo);
    __nv_bfloat16* sl = sh + W_TILE_ELEMS;
#pragma unroll 4
    for (int i = 0; i < 16; ++i) {
        int idx4 = i * 256 + t;
        int row = idx4 >> 5;
        int col = (idx4 & 31) << 2;
        int so = row * ASTRIDE + col;

        float4 w = *reinterpret_cast<const float4*>(Wn + (size_t)row * 128 + col);
        float h0 = bf16_round(w.x), h1 = bf16_round(w.y);
        float h2 = bf16_round(w.z), h3 = bf16_round(w.w);
        *reinterpret_cast<uint2*>(nh + so) = make_uint2(packbf2(h0, h1), packbf2(h2, h3));
        *reinterpret_cast<uint2*>(nl + so) =
            make_uint2(packbf2(w.x - h0, w.y - h1), packbf2(w.z - h2, w.w - h3));

        float4 v = *reinterpret_cast<const float4*>(Ws + (size_t)row * 128 + col);
        float g0 = bf16_round(v.x), g1 = bf16_round(v.y);
        float g2 = bf16_round(v.z), g3 = bf16_round(v.w);
        *reinterpret_cast<uint2*>(sh + so) = make_uint2(packbf2(g0, g1), packbf2(g2, g3));
        *reinterpret_cast<uint2*>(sl + so) =
            make_uint2(packbf2(v.x - g0, v.y - g1), packbf2(v.z - g2, v.w - g3));
    }
}

// ---------------------------------------------------------------------------
// Kernel 1: zero the aggregation buffer.
// ---------------------------------------------------------------------------
__global__ void zero_agg_kernel(int total4) {
    int i = blockIdx.x * blockDim.x + threadIdx.x;
    float4 z = make_float4(0.f, 0.f, 0.f, 0.f);
    for (; i < total4; i += gridDim.x * blockDim.x) {
        g_agg4[i] = z;
    }
}

// ---------------------------------------------------------------------------
// Kernel 2: scatter-add. One warp per edge; vector RED into L2-resident agg.
// ---------------------------------------------------------------------------
__global__ void scatter_kernel(const float* __restrict__ feat,
                               const int* __restrict__ src,
                               const int* __restrict__ dst,
                               int n_edges, int n_nodes) {
    int warps_per_block = blockDim.x >> 5;
    int e = blockIdx.x * warps_per_block + (threadIdx.x >> 5);
    if (e >= n_edges) return;
    int lane = threadIdx.x & 31;

    int s = src[e];
    int d = dst[e];
    if ((unsigned)s >= (unsigned)n_nodes || (unsigned)d >= (unsigned)n_nodes) return;

    const float4* fsrc = reinterpret_cast<const float4*>(feat) + (size_t)s * (D_FEAT / 4);
    float4 v = fsrc[lane];

    float4* dstp = g_agg4 + (size_t)d * (D_FEAT / 4) + lane;
    asm volatile("red.global.add.v4.f32 [%0], {%1, %2, %3, %4};"
                 :: "l"(dstp), "f"(v.x), "f"(v.y), "f"(v.z), "f"(v.w)
                 : "memory");
}

// ---------------------------------------------------------------------------
// Kernel 3: fused dual split-bf16 tensor-core GEMM + bias.
//   out = agg @ Wn + feat @ Ws + b, each product via 3-term bf16 split.
// 64x128 output tile (2 CTAs/SM for latency hiding), 256 threads (8 warps:
// 2 m-groups x 4 n-groups), K=128 staged whole.
// ---------------------------------------------------------------------------
__global__ __launch_bounds__(256, 2)
void gemm_kernel(const float* __restrict__ feat,
                 const float* __restrict__ bn,
                 float* __restrict__ out,
                 int n_nodes) {
    extern __shared__ char smem[];
    __nv_bfloat16* Ahi = reinterpret_cast<__nv_bfloat16*>(smem);
    __nv_bfloat16* Alo = Ahi + A_TILE_ELEMS;
    __nv_bfloat16* Whi = Alo + A_TILE_ELEMS;   // Whi+Wlo contiguous: linear copy

    const uint32_t aHi_b = smem_u32(Ahi);
    const uint32_t aLo_b = smem_u32(Alo);
    const uint32_t wHi_b = smem_u32(Whi);
    const uint32_t wLo_b = wHi_b + W_TILE_ELEMS * 2;

    int tid = threadIdx.x;
    int lane = tid & 31;
    int wid = tid >> 5;
    int wm = wid & 1;          // m-group: rows wm*32 .. +31
    int wn = wid >> 1;         // n-group: cols wn*32 .. +31
    int m0 = blockIdx.x * BLK_M;

    int lrow = lane & 15;
    int lcolh = (lane >> 4) << 3;  // 0 or 8

    const float* aggf = reinterpret_cast<const float*>(g_agg4);

    float acc[2][4][4];
#pragma unroll
    for (int mi = 0; mi < 2; mi++)
#pragma unroll
        for (int ni = 0; ni < 4; ni++)
#pragma unroll
            for (int q = 0; q < 4; q++)
                acc[mi][ni][q] = 0.f;

    for (int half = 0; half < 2; ++half) {
        const float* Aglob = half ? feat : aggf;
        const uint4* Wsrc = half ? g_Ws_hilo : g_Wn_hilo;

        __syncthreads();  // previous half's smem reads done

        // ---- copy pre-converted W (hi then lo) into smem: 4352 uint4 ----
        {
            uint4* wdst = reinterpret_cast<uint4*>(Whi);
#pragma unroll
            for (int i = 0; i < 17; ++i) {
                int idx = i * 256 + tid;        // 17*256 = 4352 exactly
                wdst[idx] = Wsrc[idx];
            }
        }

        // ---- convert A tile (64 rows) to hi/lo bf16 in smem: 8 iters ----
#pragma unroll
        for (int it = 0; it < 8; ++it) {
            int idx4 = it * 256 + tid;          // 0..2047
            int row = idx4 >> 5;                // 0..63
            int col = (idx4 & 31) << 2;

            int grow = m0 + row;
            if (grow >= n_nodes) grow = n_nodes - 1;   // clamp; stores guarded
            float4 v = *reinterpret_cast<const float4*>(Aglob + (size_t)grow * 128 + col);
            float h0 = bf16_round(v.x), h1 = bf16_round(v.y);
            float h2 = bf16_round(v.z), h3 = bf16_round(v.w);
            int so = row * ASTRIDE + col;
            *reinterpret_cast<uint2*>(Ahi + so) = make_uint2(packbf2(h0, h1), packbf2(h2, h3));
            *reinterpret_cast<uint2*>(Alo + so) =
                make_uint2(packbf2(v.x - h0, v.y - h1), packbf2(v.z - h2, v.w - h3));
        }
        __syncthreads();

        // ---- tensor-core compute over K=128 ----
#pragma unroll
        for (int ks = 0; ks < 8; ++ks) {
            int k0 = ks * 16;

            uint32_t ahi[2][4], alo[2][4];
#pragma unroll
            for (int mi = 0; mi < 2; ++mi) {
                uint32_t off = (uint32_t)((wm * 32 + mi * 16 + lrow) * ASTRIDE + k0 + lcolh) * 2;
                ldm_x4(ahi[mi], aHi_b + off);
                ldm_x4(alo[mi], aLo_b + off);
            }
            uint32_t bhi[4][2], blo[4][2];
#pragma unroll
            for (int nh = 0; nh < 2; ++nh) {
                uint32_t off = (uint32_t)((k0 + lrow) * ASTRIDE + wn * 32 + nh * 16 + lcolh) * 2;
                uint32_t t[4];
                ldm_x4_trans(t, wHi_b + off);
                bhi[2 * nh][0] = t[0]; bhi[2 * nh][1] = t[1];
                bhi[2 * nh + 1][0] = t[2]; bhi[2 * nh + 1][1] = t[3];
                ldm_x4_trans(t, wLo_b + off);
                blo[2 * nh][0] = t[0]; blo[2 * nh][1] = t[1];
                blo[2 * nh + 1][0] = t[2]; blo[2 * nh + 1][1] = t[3];
            }
#pragma unroll
            for (int mi = 0; mi < 2; ++mi)
#pragma unroll
                for (int ni = 0; ni < 4; ++ni) {
                    mma16816(acc[mi][ni], ahi[mi], bhi[ni]);
                    mma16816(acc[mi][ni], ahi[mi], blo[ni]);
                    mma16816(acc[mi][ni], alo[mi], bhi[ni]);
                }
        }
    }

    // ---- bias + store (fragment layout: rows g, g+8; cols 2tg, 2tg+1) ----
    int g = lane >> 2, tg = lane & 3;
#pragma unroll
    for (int ni = 0; ni < 4; ++ni) {
        int col = wn * 32 + ni * 8 + 2 * tg;
        float2 bv = *reinterpret_cast<const float2*>(bn + col);
#pragma unroll
        for (int mi = 0; mi < 2; ++mi) {
            int r0 = m0 + wm * 32 + mi * 16 + g;
            if (r0 < n_nodes) {
                float2 o = make_float2(acc[mi][ni][0] + bv.x, acc[mi][ni][1] + bv.y);
                *reinterpret_cast<float2*>(out + (size_t)r0 * 128 + col) = o;
            }
            int r1 = r0 + 8;
            if (r1 < n_nodes) {
                float2 o = make_float2(acc[mi][ni][2] + bv.x, acc[mi][ni][3] + bv.y);
                *reinterpret_cast<float2*>(out + (size_t)r1 * 128 + col) = o;
            }
        }
    }
}

// ---------------------------------------------------------------------------
// Launch (single stream, strictly serial — capture-safe).
// ---------------------------------------------------------------------------
extern "C" void kernel_launch(void* const* d_in, const int* in_sizes, int n_in,
                              void* d_out, int out_size) {
    const float* feat = (const float*)d_in[0];
    const int* src    = (const int*)d_in[1];   // int64 downcast to int32 by harness
    const int* dst    = (const int*)d_in[2];
    const float* Wn   = (const float*)d_in[3];
    const float* bn   = (const float*)d_in[4];
    const float* Ws   = (const float*)d_in[5];
    float* out        = (float*)d_out;

    int n_nodes = in_sizes[0] / D_FEAT;
    int n_edges = in_sizes[1];

    static bool attr_set = false;
    if (!attr_set) {
        cudaFuncSetAttribute(gemm_kernel,
                             cudaFuncAttributeMaxDynamicSharedMemorySize,
                             GEMM_SMEM_BYTES);
        attr_set = true;
    }

    // 0) pre-convert weights to hi/lo bf16 (1 block)
    convert_w_kernel<<<1, 256>>>(Wn, Ws);

    // 1) zero agg
    int total4 = n_nodes * (D_FEAT / 4);
    int zblocks = (total4 + 255) / 256;
    if (zblocks > 4096) zblocks = 4096;
    zero_agg_kernel<<<zblocks, 256>>>(total4);

    // 2) scatter-add (8 warps = 8 edges per block)
    int sblocks = (n_edges + 7) / 8;
    scatter_kernel<<<sblocks, 256>>>(feat, src, dst, n_edges, n_nodes);

    // 3) fused dual GEMM + bias (64-row tiles, 2 CTAs/SM)
    int gblocks = (n_nodes + BLK_M - 1) / BLK_M;
    gemm_kernel<<<gblocks, 256, GEMM_SMEM_BYTES>>>(feat, bn, out, n_nodes);
}